// round 1
// baseline (speedup 1.0000x reference)
#include <cuda_runtime.h>
#include <math.h>

#define Bn 8
#define Nn 256
#define Dd 256
#define DHh 64
#define BND (Bn * Nn * DHh)
#define JU 4

// scratch: Qn,Kn,Vn,Q,K,V then x_cross, x_self
__device__ float g_np[6 * BND];
__device__ float g_xcross[BND];
__device__ float g_xself[BND];

// ------------------------------------------------------------------
// 6 projections of x: slot0=Qn(n2e_q) slot1=Kn(e2n_k) slot2=Vn(e2n_v)
//                     slot3=Q(n2n_q)  slot4=K(n2n_k)  slot5=V(n2n_v)
// grid = B*N, block = 384 (6 proj x 64 dims)
// ------------------------------------------------------------------
__global__ void proj_x_kernel(
    const float* __restrict__ x, const float* __restrict__ mask,
    const float* __restrict__ W0, const float* __restrict__ b0,
    const float* __restrict__ W1, const float* __restrict__ b1,
    const float* __restrict__ W2, const float* __restrict__ b2,
    const float* __restrict__ W3, const float* __restrict__ b3,
    const float* __restrict__ W4, const float* __restrict__ b4,
    const float* __restrict__ W5, const float* __restrict__ b5)
{
    int r = blockIdx.x;
    int t = threadIdx.x;
    __shared__ float xs[Dd];
    if (t < Dd) xs[t] = x[(size_t)r * Dd + t];
    __syncthreads();

    int p = t >> 6, h = t & 63;
    const float* W;
    const float* bb;
    switch (p) {
        case 0: W = W0; bb = b0; break;
        case 1: W = W1; bb = b1; break;
        case 2: W = W2; bb = b2; break;
        case 3: W = W3; bb = b3; break;
        case 4: W = W4; bb = b4; break;
        default: W = W5; bb = b5; break;
    }
    float acc = bb[h];
    #pragma unroll 8
    for (int k = 0; k < Dd; ++k) acc = fmaf(xs[k], W[k * DHh + h], acc);
    g_np[(size_t)p * BND + (size_t)r * DHh + h] = acc * mask[r];
}

// ------------------------------------------------------------------
// Fused edge kernel: one block per (b,i). For each j (4 at a time):
//   project e[b,i,j] -> Ke,Ve,Qe (192 outputs), 3 dot reductions,
//   online softmax over j for x_cross, write e_new directly.
// grid = B*N, block = 256
// ------------------------------------------------------------------
__global__ void edge_kernel(
    const float* __restrict__ e, const float* __restrict__ mask,
    const float* __restrict__ Wk, const float* __restrict__ bk,
    const float* __restrict__ Wv, const float* __restrict__ bv,
    const float* __restrict__ Wq, const float* __restrict__ bq,
    float* __restrict__ out_e)
{
    int r = blockIdx.x;
    int b = r >> 8;
    int t = threadIdx.x;

    __shared__ __align__(16) float e_s[JU][Dd];
    __shared__ float proj_s[JU][192];
    __shared__ float Qn_s[DHh], Kni_s[DHh], Vni_s[DHh];
    __shared__ float dots_s[JU][3];
    __shared__ float xmj_s[JU];

    const float* Qn = g_np;
    const float* Kn = g_np + BND;
    const float* Vn = g_np + 2 * BND;

    if (t < DHh) {
        Qn_s[t]  = Qn[(size_t)r * DHh + t];
        Kni_s[t] = Kn[(size_t)r * DHh + t];
        Vni_s[t] = Vn[(size_t)r * DHh + t];
    }
    float xm_i = mask[r];

    int p = t >> 6, h = t & 63;
    const float* W = (p == 0) ? Wk : ((p == 1) ? Wv : Wq);
    float bias = (p == 0) ? bk[h] : ((p == 1) ? bv[h] : bq[h]);
    int wid = t >> 5, lane = t & 31;

    float m = -INFINITY, l = 0.f, oacc = 0.f;
    const float* erow = e + (size_t)r * Nn * Dd;

    for (int j0 = 0; j0 < Nn; j0 += JU) {
        __syncthreads();
        #pragma unroll
        for (int q = 0; q < JU; ++q)
            e_s[q][t] = erow[(size_t)(j0 + q) * Dd + t];
        if (t < JU) xmj_s[t] = mask[b * Nn + j0 + t];
        __syncthreads();

        if (t < 192) {
            float a0 = bias, a1 = bias, a2 = bias, a3 = bias;
            #pragma unroll 4
            for (int k = 0; k < Dd; k += 4) {
                float4 e0 = *reinterpret_cast<const float4*>(&e_s[0][k]);
                float4 e1 = *reinterpret_cast<const float4*>(&e_s[1][k]);
                float4 e2 = *reinterpret_cast<const float4*>(&e_s[2][k]);
                float4 e3 = *reinterpret_cast<const float4*>(&e_s[3][k]);
                float w0 = W[(k + 0) * DHh + h];
                float w1 = W[(k + 1) * DHh + h];
                float w2 = W[(k + 2) * DHh + h];
                float w3 = W[(k + 3) * DHh + h];
                a0 = fmaf(e0.x, w0, a0); a0 = fmaf(e0.y, w1, a0);
                a0 = fmaf(e0.z, w2, a0); a0 = fmaf(e0.w, w3, a0);
                a1 = fmaf(e1.x, w0, a1); a1 = fmaf(e1.y, w1, a1);
                a1 = fmaf(e1.z, w2, a1); a1 = fmaf(e1.w, w3, a1);
                a2 = fmaf(e2.x, w0, a2); a2 = fmaf(e2.y, w1, a2);
                a2 = fmaf(e2.z, w2, a2); a2 = fmaf(e2.w, w3, a2);
                a3 = fmaf(e3.x, w0, a3); a3 = fmaf(e3.y, w1, a3);
                a3 = fmaf(e3.z, w2, a3); a3 = fmaf(e3.w, w3, a3);
            }
            proj_s[0][t] = a0; proj_s[1][t] = a1;
            proj_s[2][t] = a2; proj_s[3][t] = a3;
        }
        __syncthreads();

        // 12 dot products (4 j's x {Qn.Ke, Qe.Kn_j, Qe.Kn_i}) by 8 warps
        for (int dd = wid; dd < 12; dd += 8) {
            int jj = dd / 3, pd = dd % 3;
            float v;
            if (pd == 0) {
                v = proj_s[jj][lane] * Qn_s[lane]
                  + proj_s[jj][lane + 32] * Qn_s[lane + 32];
            } else if (pd == 1) {
                const float* Knj = Kn + (size_t)(b * Nn + j0 + jj) * DHh;
                v = proj_s[jj][128 + lane] * Knj[lane]
                  + proj_s[jj][128 + lane + 32] * Knj[lane + 32];
            } else {
                v = proj_s[jj][128 + lane] * Kni_s[lane]
                  + proj_s[jj][128 + lane + 32] * Kni_s[lane + 32];
            }
            #pragma unroll
            for (int o = 16; o; o >>= 1) v += __shfl_xor_sync(0xffffffffu, v, o);
            if (lane == 0) dots_s[jj][pd] = v;
        }
        __syncthreads();

        if (t < 64) {
            #pragma unroll
            for (int q = 0; q < JU; ++q) {
                float em = xm_i * xmj_s[q];
                bool am = em > 0.f;
                // n2e attention (online softmax over j)
                float s = am ? dots_s[q][0] * em * 0.125f : -1e9f;
                float mn = fmaxf(m, s);
                float pv = __expf(s - mn);
                float alpha = __expf(m - mn);
                l = l * alpha + pv;
                float Ve = proj_s[q][64 + t] * em;
                oacc = oacc * alpha + pv * Ve;
                m = mn;
                // e2n gating -> e_new
                float ai = am ? __expf(dots_s[q][1] * em * 0.125f) : 1e-9f;
                float aj = am ? __expf(dots_s[q][2] * em * 0.125f) : 1e-9f;
                float asum = am ? (ai + aj) : 1e-9f;
                float inv = 1.f / asum;
                ai *= inv; aj *= inv;
                float Vnj = Vn[(size_t)(b * Nn + j0 + q) * DHh + t];
                out_e[((size_t)r * Nn + (j0 + q)) * DHh + t] =
                    (ai * Vnj + aj * Vni_s[t]) * em;
            }
        }
    }
    if (t < 64) g_xcross[(size_t)r * DHh + t] = oacc / l;
}

// ------------------------------------------------------------------
// n2n self attention: one block per (b,i). K tiled in smem (pad 65).
// grid = B*N, block = 256
// ------------------------------------------------------------------
__global__ void self_attn_kernel(const float* __restrict__ mask)
{
    int r = blockIdx.x;
    int b = r >> 8;
    int t = threadIdx.x;

    __shared__ float Q_s[DHh];
    __shared__ float K_s[128][65];
    __shared__ float att[Nn];
    __shared__ float red[256];

    const float* Q = g_np + 3 * (size_t)BND;
    const float* K = g_np + 4 * (size_t)BND;
    const float* V = g_np + 5 * (size_t)BND;

    if (t < DHh) Q_s[t] = Q[(size_t)r * DHh + t];
    float xm_i = mask[r];
    float logit = 0.f;

    for (int tt = 0; tt < 2; ++tt) {
        __syncthreads();
        for (int idx = t; idx < 128 * 64; idx += 256) {
            int row = idx >> 6, col = idx & 63;
            K_s[row][col] = K[(size_t)(b * Nn + tt * 128 + row) * DHh + col];
        }
        __syncthreads();
        if ((t >> 7) == tt) {
            int row = t & 127;
            float a = 0.f;
            #pragma unroll 8
            for (int k = 0; k < DHh; ++k) a = fmaf(Q_s[k], K_s[row][k], a);
            logit = a;
        }
    }

    float xm_j = mask[b * Nn + t];
    bool am = (xm_i * xm_j) > 0.f;
    logit = am ? logit * 0.125f : -1e9f;

    red[t] = logit;
    __syncthreads();
    for (int o = 128; o; o >>= 1) {
        if (t < o) red[t] = fmaxf(red[t], red[t + o]);
        __syncthreads();
    }
    float mx = red[0];
    __syncthreads();
    float ex = __expf(logit - mx);
    red[t] = ex;
    __syncthreads();
    for (int o = 128; o; o >>= 1) {
        if (t < o) red[t] += red[t + o];
        __syncthreads();
    }
    float sm = red[0];
    att[t] = ex / sm;
    __syncthreads();

    if (t < DHh) {
        float acc = 0.f;
        for (int j = 0; j < Nn; ++j)
            acc = fmaf(att[j], V[(size_t)(b * Nn + j) * DHh + t], acc);
        g_xself[(size_t)r * DHh + t] = acc * xm_i;
    }
}

// ------------------------------------------------------------------
// x_out = concat(x_cross, x_self) @ W_mix + b_mix
// grid = B*N, block = 64
// ------------------------------------------------------------------
__global__ void mix_kernel(const float* __restrict__ Wmix,
                           const float* __restrict__ bmix,
                           float* __restrict__ out)
{
    int r = blockIdx.x, t = threadIdx.x;
    __shared__ float xc[DHh], xs[DHh];
    xc[t] = g_xcross[(size_t)r * DHh + t];
    xs[t] = g_xself[(size_t)r * DHh + t];
    __syncthreads();
    float acc = bmix[t];
    #pragma unroll 8
    for (int k = 0; k < DHh; ++k) {
        acc = fmaf(xc[k], Wmix[k * DHh + t], acc);
        acc = fmaf(xs[k], Wmix[(DHh + k) * DHh + t], acc);
    }
    out[(size_t)r * DHh + t] = acc;
}

extern "C" void kernel_launch(void* const* d_in, const int* in_sizes, int n_in,
                              void* d_out, int out_size)
{
    const float* x       = (const float*)d_in[0];
    const float* e       = (const float*)d_in[1];
    const float* mask    = (const float*)d_in[2];
    const float* W_n2e_q = (const float*)d_in[3];  const float* b_n2e_q = (const float*)d_in[4];
    const float* W_n2e_k = (const float*)d_in[5];  const float* b_n2e_k = (const float*)d_in[6];
    const float* W_n2e_v = (const float*)d_in[7];  const float* b_n2e_v = (const float*)d_in[8];
    const float* W_e2n_q = (const float*)d_in[9];  const float* b_e2n_q = (const float*)d_in[10];
    const float* W_e2n_k = (const float*)d_in[11]; const float* b_e2n_k = (const float*)d_in[12];
    const float* W_e2n_v = (const float*)d_in[13]; const float* b_e2n_v = (const float*)d_in[14];
    const float* W_n2n_q = (const float*)d_in[15]; const float* b_n2n_q = (const float*)d_in[16];
    const float* W_n2n_k = (const float*)d_in[17]; const float* b_n2n_k = (const float*)d_in[18];
    const float* W_n2n_v = (const float*)d_in[19]; const float* b_n2n_v = (const float*)d_in[20];
    const float* W_mix   = (const float*)d_in[21]; const float* b_mix   = (const float*)d_in[22];

    float* out   = (float*)d_out;
    float* out_x = out;                              // (B,N,DH)
    float* out_e = out + (size_t)Bn * Nn * DHh;      // (B,N,N,DH)

    proj_x_kernel<<<Bn * Nn, 384>>>(x, mask,
        W_n2e_q, b_n2e_q,   // Qn
        W_e2n_k, b_e2n_k,   // Kn
        W_e2n_v, b_e2n_v,   // Vn
        W_n2n_q, b_n2n_q,   // Q
        W_n2n_k, b_n2n_k,   // K
        W_n2n_v, b_n2n_v);  // V

    edge_kernel<<<Bn * Nn, 256>>>(e, mask,
        W_n2e_k, b_n2e_k, W_n2e_v, b_n2e_v, W_e2n_q, b_e2n_q, out_e);

    self_attn_kernel<<<Bn * Nn, 256>>>(mask);

    mix_kernel<<<Bn * Nn, 64>>>(W_mix, b_mix, out_x);
}

// round 2
// speedup vs baseline: 9.0474x; 9.0474x over previous
#include <cuda_runtime.h>
#include <math.h>

#define Bn 8
#define Nn 256
#define Dd 256
#define DHh 64
#define BND (Bn * Nn * DHh)      // 131072
#define BNr (Bn * Nn)            // 2048

// scratch: Qn,Kn,Vn,Q,K,V
__device__ float g_np[6 * BND];
__device__ float g_xself[BND];
// folded-weight per-row vectors
__device__ float g_u[BNr * Dd];    // Wk_n2e @ Qn_i
__device__ float g_v[BNr * Dd];    // Wq_e2n @ Kn_j
__device__ float g_c[BNr];         // bk_n2e . Qn_i
__device__ float g_d[BNr];         // bq_e2n . Kn_j
// transposed weights (h-major)
__device__ float g_Wkt[DHh * Dd];
__device__ float g_Wqt[DHh * Dd];
// softmax-weighted e sum and scalar
__device__ float g_s[BNr * Dd];
__device__ float g_t[BNr];

// ------------------------------------------------------------------
// 6 projections of x: slot0=Qn(n2e_q) slot1=Kn(e2n_k) slot2=Vn(e2n_v)
//                     slot3=Q(n2n_q)  slot4=K(n2n_k)  slot5=V(n2n_v)
// ------------------------------------------------------------------
__global__ void proj_x_kernel(
    const float* __restrict__ x, const float* __restrict__ mask,
    const float* __restrict__ W0, const float* __restrict__ b0,
    const float* __restrict__ W1, const float* __restrict__ b1,
    const float* __restrict__ W2, const float* __restrict__ b2,
    const float* __restrict__ W3, const float* __restrict__ b3,
    const float* __restrict__ W4, const float* __restrict__ b4,
    const float* __restrict__ W5, const float* __restrict__ b5)
{
    int r = blockIdx.x;
    int t = threadIdx.x;
    __shared__ float xs[Dd];
    if (t < Dd) xs[t] = x[(size_t)r * Dd + t];
    __syncthreads();

    int p = t >> 6, h = t & 63;
    const float* W;
    const float* bb;
    switch (p) {
        case 0: W = W0; bb = b0; break;
        case 1: W = W1; bb = b1; break;
        case 2: W = W2; bb = b2; break;
        case 3: W = W3; bb = b3; break;
        case 4: W = W4; bb = b4; break;
        default: W = W5; bb = b5; break;
    }
    float acc = bb[h];
    #pragma unroll 8
    for (int k = 0; k < Dd; ++k) acc = fmaf(xs[k], W[k * DHh + h], acc);
    g_np[(size_t)p * BND + (size_t)r * DHh + h] = acc * mask[r];
}

// transpose the two folded weights into h-major layout (coalesced reads later)
__global__ void transpose_w_kernel(const float* __restrict__ Wk,
                                   const float* __restrict__ Wq)
{
    int h = blockIdx.x;       // 64
    int d = threadIdx.x;      // 256
    g_Wkt[h * Dd + d] = Wk[d * DHh + h];
    g_Wqt[h * Dd + d] = Wq[d * DHh + h];
}

// u_r[d] = sum_h Wkt[h][d]*Qn_r[h];  v_r[d] = sum_h Wqt[h][d]*Kn_r[h]
// c_r = bk.Qn_r; d_r = bq.Kn_r
__global__ void make_uv_kernel(const float* __restrict__ bk,
                               const float* __restrict__ bq)
{
    int r = blockIdx.x;
    int t = threadIdx.x;    // 256 = one d each
    __shared__ float qn[DHh], kn[DHh], pc[DHh], pd[DHh];
    if (t < DHh) {
        float q = g_np[(size_t)r * DHh + t];            // Qn
        float k = g_np[(size_t)(BND) + (size_t)r * DHh + t];  // Kn
        qn[t] = q; kn[t] = k;
        pc[t] = bk[t] * q;
        pd[t] = bq[t] * k;
    }
    __syncthreads();
    float au = 0.f, av = 0.f;
    #pragma unroll 8
    for (int h = 0; h < DHh; ++h) {
        au = fmaf(g_Wkt[h * Dd + t], qn[h], au);
        av = fmaf(g_Wqt[h * Dd + t], kn[h], av);
    }
    g_u[(size_t)r * Dd + t] = au;
    g_v[(size_t)r * Dd + t] = av;
    if (t == 0) {
        float sc = 0.f, sd2 = 0.f;
        #pragma unroll
        for (int h = 0; h < DHh; ++h) { sc += pc[h]; sd2 += pd[h]; }
        g_c[r] = sc;
        g_d[r] = sd2;
    }
}

// ------------------------------------------------------------------
// Fused edge kernel: one block per (b,i); each warp streams 32 j-rows
// of e, computes 3 dots vs precomputed u_i / v_j / v_i, maintains an
// online-softmax 256-dim weighted sum of e (for x_cross), and writes
// e_new directly. Single pass over e.
// ------------------------------------------------------------------
__global__ void edge_kernel(const float* __restrict__ e,
                            const float* __restrict__ mask,
                            float* __restrict__ out_e)
{
    int r = blockIdx.x;
    int b = r >> 8;
    int t = threadIdx.x;
    int wid = t >> 5, lane = t & 31;

    const float* Vn = g_np + 2 * (size_t)BND;

    int d0 = 4 * lane;         // dims [d0, d0+4)
    int d1 = 128 + 4 * lane;   // dims [d1, d1+4)

    const float4 u0 = *reinterpret_cast<const float4*>(g_u + (size_t)r * Dd + d0);
    const float4 u1 = *reinterpret_cast<const float4*>(g_u + (size_t)r * Dd + d1);
    const float4 vi0 = *reinterpret_cast<const float4*>(g_v + (size_t)r * Dd + d0);
    const float4 vi1 = *reinterpret_cast<const float4*>(g_v + (size_t)r * Dd + d1);
    const float c_i = g_c[r];
    const float di  = g_d[r];
    const float xm_i = mask[r];
    const float vni0 = Vn[(size_t)r * DHh + 2 * lane];
    const float vni1 = Vn[(size_t)r * DHh + 2 * lane + 1];

    float m = -INFINITY, l = 0.f, tacc = 0.f;
    float4 s0 = make_float4(0.f, 0.f, 0.f, 0.f);
    float4 s1 = make_float4(0.f, 0.f, 0.f, 0.f);

    for (int j = wid; j < Nn; j += 8) {
        const float* ep = e + ((size_t)r * Nn + j) * Dd;
        float4 e0 = __ldcs(reinterpret_cast<const float4*>(ep + d0));
        float4 e1 = __ldcs(reinterpret_cast<const float4*>(ep + d1));
        const float* vp = g_v + (size_t)(b * Nn + j) * Dd;
        float4 vj0 = *reinterpret_cast<const float4*>(vp + d0);
        float4 vj1 = *reinterpret_cast<const float4*>(vp + d1);
        float xm_j = mask[b * Nn + j];
        float dj   = g_d[b * Nn + j];

        float dot0, dot1, dot2;
        dot0 = e0.x * u0.x;              dot0 = fmaf(e0.y, u0.y, dot0);
        dot0 = fmaf(e0.z, u0.z, dot0);   dot0 = fmaf(e0.w, u0.w, dot0);
        dot0 = fmaf(e1.x, u1.x, dot0);   dot0 = fmaf(e1.y, u1.y, dot0);
        dot0 = fmaf(e1.z, u1.z, dot0);   dot0 = fmaf(e1.w, u1.w, dot0);
        dot1 = e0.x * vj0.x;             dot1 = fmaf(e0.y, vj0.y, dot1);
        dot1 = fmaf(e0.z, vj0.z, dot1);  dot1 = fmaf(e0.w, vj0.w, dot1);
        dot1 = fmaf(e1.x, vj1.x, dot1);  dot1 = fmaf(e1.y, vj1.y, dot1);
        dot1 = fmaf(e1.z, vj1.z, dot1);  dot1 = fmaf(e1.w, vj1.w, dot1);
        dot2 = e0.x * vi0.x;             dot2 = fmaf(e0.y, vi0.y, dot2);
        dot2 = fmaf(e0.z, vi0.z, dot2);  dot2 = fmaf(e0.w, vi0.w, dot2);
        dot2 = fmaf(e1.x, vi1.x, dot2);  dot2 = fmaf(e1.y, vi1.y, dot2);
        dot2 = fmaf(e1.z, vi1.z, dot2);  dot2 = fmaf(e1.w, vi1.w, dot2);

        #pragma unroll
        for (int o = 16; o; o >>= 1) {
            dot0 += __shfl_xor_sync(0xffffffffu, dot0, o);
            dot1 += __shfl_xor_sync(0xffffffffu, dot1, o);
            dot2 += __shfl_xor_sync(0xffffffffu, dot2, o);
        }

        float em = xm_i * xm_j;
        bool am = em > 0.f;

        // n2e online softmax + weighted e accumulation
        float sc = am ? (dot0 + c_i) * em * 0.125f : -1e9f;
        float mn = fmaxf(m, sc);
        float alpha = __expf(m - mn);
        float pv = __expf(sc - mn);
        l = l * alpha + pv;
        float pve = pv * em;
        tacc = tacc * alpha + pve;
        s0.x = fmaf(s0.x, alpha, pve * e0.x);
        s0.y = fmaf(s0.y, alpha, pve * e0.y);
        s0.z = fmaf(s0.z, alpha, pve * e0.z);
        s0.w = fmaf(s0.w, alpha, pve * e0.w);
        s1.x = fmaf(s1.x, alpha, pve * e1.x);
        s1.y = fmaf(s1.y, alpha, pve * e1.y);
        s1.z = fmaf(s1.z, alpha, pve * e1.z);
        s1.w = fmaf(s1.w, alpha, pve * e1.w);
        m = mn;

        // e2n gating -> e_new (each lane writes 2 head dims)
        float o0 = 0.f, o1 = 0.f;
        if (am) {
            float z1 = __expf((dot1 + dj) * em * 0.125f);
            float z2 = __expf((dot2 + di) * em * 0.125f);
            float inv = 1.f / (z1 + z2);
            float ai = z1 * inv, aj = z2 * inv;
            float vnj0 = Vn[(size_t)(b * Nn + j) * DHh + 2 * lane];
            float vnj1 = Vn[(size_t)(b * Nn + j) * DHh + 2 * lane + 1];
            o0 = (ai * vnj0 + aj * vni0) * em;
            o1 = (ai * vnj1 + aj * vni1) * em;
        }
        *reinterpret_cast<float2*>(out_e + ((size_t)r * Nn + j) * DHh + 2 * lane)
            = make_float2(o0, o1);
    }

    // merge the 8 warps' online-softmax partials
    __shared__ float s_sm[8][Dd];
    __shared__ float mw[8], lw[8], tw[8];
    s_sm[wid][d0 + 0] = s0.x; s_sm[wid][d0 + 1] = s0.y;
    s_sm[wid][d0 + 2] = s0.z; s_sm[wid][d0 + 3] = s0.w;
    s_sm[wid][d1 + 0] = s1.x; s_sm[wid][d1 + 1] = s1.y;
    s_sm[wid][d1 + 2] = s1.z; s_sm[wid][d1 + 3] = s1.w;
    if (lane == 0) { mw[wid] = m; lw[wid] = l; tw[wid] = tacc; }
    __syncthreads();

    float gm = mw[0];
    #pragma unroll
    for (int w = 1; w < 8; ++w) gm = fmaxf(gm, mw[w]);
    float gl = 0.f, gt = 0.f, gs = 0.f;
    #pragma unroll
    for (int w = 0; w < 8; ++w) {
        float sc2 = __expf(mw[w] - gm);
        gl = fmaf(lw[w], sc2, gl);
        gt = fmaf(tw[w], sc2, gt);
        gs = fmaf(s_sm[w][t], sc2, gs);
    }
    float invl = 1.f / gl;
    g_s[(size_t)r * Dd + t] = gs * invl;
    if (t == 0) g_t[r] = gt * invl;
}

// ------------------------------------------------------------------
// n2n self attention: one block per (b,i).
// ------------------------------------------------------------------
__global__ void self_attn_kernel(const float* __restrict__ mask)
{
    int r = blockIdx.x;
    int b = r >> 8;
    int t = threadIdx.x;

    __shared__ float Q_s[DHh];
    __shared__ float K_s[128][65];
    __shared__ float att[Nn];
    __shared__ float red[256];

    const float* Q = g_np + 3 * (size_t)BND;
    const float* K = g_np + 4 * (size_t)BND;
    const float* V = g_np + 5 * (size_t)BND;

    if (t < DHh) Q_s[t] = Q[(size_t)r * DHh + t];
    float xm_i = mask[r];
    float logit = 0.f;

    for (int tt = 0; tt < 2; ++tt) {
        __syncthreads();
        for (int idx = t; idx < 128 * 64; idx += 256) {
            int row = idx >> 6, col = idx & 63;
            K_s[row][col] = K[(size_t)(b * Nn + tt * 128 + row) * DHh + col];
        }
        __syncthreads();
        if ((t >> 7) == tt) {
            int row = t & 127;
            float a = 0.f;
            #pragma unroll 8
            for (int k = 0; k < DHh; ++k) a = fmaf(Q_s[k], K_s[row][k], a);
            logit = a;
        }
    }

    float xm_j = mask[b * Nn + t];
    bool am = (xm_i * xm_j) > 0.f;
    logit = am ? logit * 0.125f : -1e9f;

    red[t] = logit;
    __syncthreads();
    for (int o = 128; o; o >>= 1) {
        if (t < o) red[t] = fmaxf(red[t], red[t + o]);
        __syncthreads();
    }
    float mx = red[0];
    __syncthreads();
    float ex = __expf(logit - mx);
    red[t] = ex;
    __syncthreads();
    for (int o = 128; o; o >>= 1) {
        if (t < o) red[t] += red[t + o];
        __syncthreads();
    }
    float sm = red[0];
    att[t] = ex / sm;
    __syncthreads();

    if (t < DHh) {
        float acc = 0.f;
        for (int j = 0; j < Nn; ++j)
            acc = fmaf(att[j], V[(size_t)(b * Nn + j) * DHh + t], acc);
        g_xself[(size_t)r * DHh + t] = acc * xm_i;
    }
}

// ------------------------------------------------------------------
// x_cross = g_s @ Wv + g_t*bv ; x_out = [x_cross, x_self] @ Wmix + bmix
// grid = B*N, block = 64
// ------------------------------------------------------------------
__global__ void xcross_mix_kernel(const float* __restrict__ Wv,
                                  const float* __restrict__ bv,
                                  const float* __restrict__ Wmix,
                                  const float* __restrict__ bmix,
                                  float* __restrict__ out)
{
    int r = blockIdx.x, t = threadIdx.x;
    __shared__ float ssm[Dd];
    __shared__ float xc[DHh], xsf[DHh];
    #pragma unroll
    for (int q = 0; q < 4; ++q) ssm[t + 64 * q] = g_s[(size_t)r * Dd + t + 64 * q];
    xsf[t] = g_xself[(size_t)r * DHh + t];
    __syncthreads();

    float acc = g_t[r] * bv[t];
    #pragma unroll 8
    for (int d = 0; d < Dd; ++d) acc = fmaf(ssm[d], Wv[d * DHh + t], acc);
    xc[t] = acc;
    __syncthreads();

    float o = bmix[t];
    #pragma unroll 8
    for (int k = 0; k < DHh; ++k) {
        o = fmaf(xc[k], Wmix[k * DHh + t], o);
        o = fmaf(xsf[k], Wmix[(DHh + k) * DHh + t], o);
    }
    out[(size_t)r * DHh + t] = o;
}

extern "C" void kernel_launch(void* const* d_in, const int* in_sizes, int n_in,
                              void* d_out, int out_size)
{
    const float* x       = (const float*)d_in[0];
    const float* e       = (const float*)d_in[1];
    const float* mask    = (const float*)d_in[2];
    const float* W_n2e_q = (const float*)d_in[3];  const float* b_n2e_q = (const float*)d_in[4];
    const float* W_n2e_k = (const float*)d_in[5];  const float* b_n2e_k = (const float*)d_in[6];
    const float* W_n2e_v = (const float*)d_in[7];  const float* b_n2e_v = (const float*)d_in[8];
    const float* W_e2n_q = (const float*)d_in[9];  const float* b_e2n_q = (const float*)d_in[10];
    const float* W_e2n_k = (const float*)d_in[11]; const float* b_e2n_k = (const float*)d_in[12];
    const float* W_e2n_v = (const float*)d_in[13]; const float* b_e2n_v = (const float*)d_in[14];
    const float* W_n2n_q = (const float*)d_in[15]; const float* b_n2n_q = (const float*)d_in[16];
    const float* W_n2n_k = (const float*)d_in[17]; const float* b_n2n_k = (const float*)d_in[18];
    const float* W_n2n_v = (const float*)d_in[19]; const float* b_n2n_v = (const float*)d_in[20];
    const float* W_mix   = (const float*)d_in[21]; const float* b_mix   = (const float*)d_in[22];

    float* out   = (float*)d_out;
    float* out_x = out;
    float* out_e = out + (size_t)Bn * Nn * DHh;

    proj_x_kernel<<<BNr, 384>>>(x, mask,
        W_n2e_q, b_n2e_q,   // Qn
        W_e2n_k, b_e2n_k,   // Kn
        W_e2n_v, b_e2n_v,   // Vn
        W_n2n_q, b_n2n_q,   // Q
        W_n2n_k, b_n2n_k,   // K
        W_n2n_v, b_n2n_v);  // V

    transpose_w_kernel<<<DHh, Dd>>>(W_n2e_k, W_e2n_q);
    make_uv_kernel<<<BNr, Dd>>>(b_n2e_k, b_e2n_q);

    edge_kernel<<<BNr, 256>>>(e, mask, out_e);

    self_attn_kernel<<<BNr, 256>>>(mask);

    xcross_mix_kernel<<<BNr, 64>>>(W_n2e_v, b_n2e_v, W_mix, b_mix, out_x);
}

// round 4
// speedup vs baseline: 11.3690x; 1.2566x over previous
#include <cuda_runtime.h>
#include <math.h>

#define Bn 8
#define Nn 256
#define Dd 256
#define DHh 64
#define BND (Bn * Nn * DHh)      // 131072
#define BNr (Bn * Nn)            // 2048

// scratch: Qn,Kn,Vn,Q,K,V
__device__ float g_np[6 * BND];
__device__ float g_xself[BND];
// folded-weight per-row vectors
__device__ float g_u[BNr * Dd];    // Wk_n2e @ Qn_i
__device__ float g_v[BNr * Dd];    // Wq_e2n @ Kn_j
__device__ float g_c[BNr];         // bk_n2e . Qn_i
__device__ float g_d[BNr];         // bq_e2n . Kn_j
// transposed weights (h-major)
__device__ float g_Wkt[DHh * Dd];
__device__ float g_Wqt[DHh * Dd];
// softmax-weighted e sum and scalar
__device__ float g_s[BNr * Dd];
__device__ float g_t[BNr];

__device__ __forceinline__ float warp_sum(float v) {
    #pragma unroll
    for (int o = 16; o; o >>= 1) v += __shfl_xor_sync(0xffffffffu, v, o);
    return v;
}

// ------------------------------------------------------------------
// 6 projections of x
// ------------------------------------------------------------------
__global__ void proj_x_kernel(
    const float* __restrict__ x, const float* __restrict__ mask,
    const float* __restrict__ W0, const float* __restrict__ b0,
    const float* __restrict__ W1, const float* __restrict__ b1,
    const float* __restrict__ W2, const float* __restrict__ b2,
    const float* __restrict__ W3, const float* __restrict__ b3,
    const float* __restrict__ W4, const float* __restrict__ b4,
    const float* __restrict__ W5, const float* __restrict__ b5)
{
    int r = blockIdx.x;
    int t = threadIdx.x;
    __shared__ float xs[Dd];
    if (t < Dd) xs[t] = x[(size_t)r * Dd + t];
    __syncthreads();

    int p = t >> 6, h = t & 63;
    const float* W;
    const float* bb;
    switch (p) {
        case 0: W = W0; bb = b0; break;
        case 1: W = W1; bb = b1; break;
        case 2: W = W2; bb = b2; break;
        case 3: W = W3; bb = b3; break;
        case 4: W = W4; bb = b4; break;
        default: W = W5; bb = b5; break;
    }
    float acc = bb[h];
    #pragma unroll 8
    for (int k = 0; k < Dd; ++k) acc = fmaf(xs[k], W[k * DHh + h], acc);
    g_np[(size_t)p * BND + (size_t)r * DHh + h] = acc * mask[r];
}

__global__ void transpose_w_kernel(const float* __restrict__ Wk,
                                   const float* __restrict__ Wq)
{
    int h = blockIdx.x;
    int d = threadIdx.x;
    g_Wkt[h * Dd + d] = Wk[d * DHh + h];
    g_Wqt[h * Dd + d] = Wq[d * DHh + h];
}

__global__ void make_uv_kernel(const float* __restrict__ bk,
                               const float* __restrict__ bq)
{
    int r = blockIdx.x;
    int t = threadIdx.x;    // 256
    __shared__ float qn[DHh], kn[DHh], pc[DHh], pd[DHh];
    if (t < DHh) {
        float q = g_np[(size_t)r * DHh + t];
        float k = g_np[(size_t)BND + (size_t)r * DHh + t];
        qn[t] = q; kn[t] = k;
        pc[t] = bk[t] * q;
        pd[t] = bq[t] * k;
    }
    __syncthreads();
    float au = 0.f, av = 0.f;
    #pragma unroll 8
    for (int h = 0; h < DHh; ++h) {
        au = fmaf(g_Wkt[h * Dd + t], qn[h], au);
        av = fmaf(g_Wqt[h * Dd + t], kn[h], av);
    }
    g_u[(size_t)r * Dd + t] = au;
    g_v[(size_t)r * Dd + t] = av;
    if (t == 0) {
        float sc = 0.f, sd2 = 0.f;
        #pragma unroll
        for (int h = 0; h < DHh; ++h) { sc += pc[h]; sd2 += pd[h]; }
        g_c[r] = sc;
        g_d[r] = sd2;
    }
}

// ------------------------------------------------------------------
// Fused edge kernel, software-pipelined, 2 warp reductions per j:
//   dot0 = e.u_i   (n2e logit)
//   dotd = e.(v_j - v_i)  -> gate ai = sigmoid((dotd + dj - di)*em/8)
// ------------------------------------------------------------------
__global__ void edge_kernel(const float* __restrict__ e,
                            const float* __restrict__ mask,
                            float* __restrict__ out_e)
{
    int r = blockIdx.x;
    int b = r >> 8;
    int t = threadIdx.x;
    int wid = t >> 5, lane = t & 31;

    const float* Vn = g_np + 2 * (size_t)BND;

    int d0 = 4 * lane;
    int d1 = 128 + 4 * lane;

    const float4 u0  = *reinterpret_cast<const float4*>(g_u + (size_t)r * Dd + d0);
    const float4 u1  = *reinterpret_cast<const float4*>(g_u + (size_t)r * Dd + d1);
    const float4 vi0 = *reinterpret_cast<const float4*>(g_v + (size_t)r * Dd + d0);
    const float4 vi1 = *reinterpret_cast<const float4*>(g_v + (size_t)r * Dd + d1);
    const float c_i  = g_c[r];
    const float di   = g_d[r];
    const float xm_i = mask[r];
    const float2 vni = *reinterpret_cast<const float2*>(Vn + (size_t)r * DHh + 2 * lane);

    float m = -INFINITY, l = 0.f, tacc = 0.f;
    float4 s0 = make_float4(0.f, 0.f, 0.f, 0.f);
    float4 s1 = make_float4(0.f, 0.f, 0.f, 0.f);

    const float* erow = e + (size_t)r * Nn * Dd;

    // ---- prologue: load j = wid ----
    int j = wid;
    float4 e0 = __ldcs(reinterpret_cast<const float4*>(erow + (size_t)j * Dd + d0));
    float4 e1 = __ldcs(reinterpret_cast<const float4*>(erow + (size_t)j * Dd + d1));
    float4 vj0 = *reinterpret_cast<const float4*>(g_v + (size_t)(b * Nn + j) * Dd + d0);
    float4 vj1 = *reinterpret_cast<const float4*>(g_v + (size_t)(b * Nn + j) * Dd + d1);
    float2 vnj = *reinterpret_cast<const float2*>(Vn + (size_t)(b * Nn + j) * DHh + 2 * lane);
    float xm_j = mask[b * Nn + j];
    float dj   = g_d[b * Nn + j];

    for (; j < Nn; ) {
        int jn = j + 8;
        float4 ne0, ne1, nvj0, nvj1; float2 nvnj; float nxm_j = 0.f, ndj = 0.f;
        if (jn < Nn) {
            ne0 = __ldcs(reinterpret_cast<const float4*>(erow + (size_t)jn * Dd + d0));
            ne1 = __ldcs(reinterpret_cast<const float4*>(erow + (size_t)jn * Dd + d1));
            nvj0 = *reinterpret_cast<const float4*>(g_v + (size_t)(b * Nn + jn) * Dd + d0);
            nvj1 = *reinterpret_cast<const float4*>(g_v + (size_t)(b * Nn + jn) * Dd + d1);
            nvnj = *reinterpret_cast<const float2*>(Vn + (size_t)(b * Nn + jn) * DHh + 2 * lane);
            nxm_j = mask[b * Nn + jn];
            ndj   = g_d[b * Nn + jn];
        }

        // vdiff = v_j - v_i
        float4 w0, w1;
        w0.x = vj0.x - vi0.x; w0.y = vj0.y - vi0.y;
        w0.z = vj0.z - vi0.z; w0.w = vj0.w - vi0.w;
        w1.x = vj1.x - vi1.x; w1.y = vj1.y - vi1.y;
        w1.z = vj1.z - vi1.z; w1.w = vj1.w - vi1.w;

        float dot0, dotd;
        dot0 = e0.x * u0.x;              dot0 = fmaf(e0.y, u0.y, dot0);
        dot0 = fmaf(e0.z, u0.z, dot0);   dot0 = fmaf(e0.w, u0.w, dot0);
        dot0 = fmaf(e1.x, u1.x, dot0);   dot0 = fmaf(e1.y, u1.y, dot0);
        dot0 = fmaf(e1.z, u1.z, dot0);   dot0 = fmaf(e1.w, u1.w, dot0);
        dotd = e0.x * w0.x;              dotd = fmaf(e0.y, w0.y, dotd);
        dotd = fmaf(e0.z, w0.z, dotd);   dotd = fmaf(e0.w, w0.w, dotd);
        dotd = fmaf(e1.x, w1.x, dotd);   dotd = fmaf(e1.y, w1.y, dotd);
        dotd = fmaf(e1.z, w1.z, dotd);   dotd = fmaf(e1.w, w1.w, dotd);

        // two independent butterfly chains (interleaved by compiler)
        #pragma unroll
        for (int o = 16; o; o >>= 1) {
            dot0 += __shfl_xor_sync(0xffffffffu, dot0, o);
            dotd += __shfl_xor_sync(0xffffffffu, dotd, o);
        }

        float em = xm_i * xm_j;
        bool am = em > 0.f;

        // n2e online softmax + weighted-e accumulation
        float sc = am ? (dot0 + c_i) * em * 0.125f : -1e9f;
        float mn = fmaxf(m, sc);
        float alpha = __expf(m - mn);
        float pv = __expf(sc - mn);
        l = l * alpha + pv;
        float pve = pv * em;
        tacc = tacc * alpha + pve;
        s0.x = fmaf(s0.x, alpha, pve * e0.x);
        s0.y = fmaf(s0.y, alpha, pve * e0.y);
        s0.z = fmaf(s0.z, alpha, pve * e0.z);
        s0.w = fmaf(s0.w, alpha, pve * e0.w);
        s1.x = fmaf(s1.x, alpha, pve * e1.x);
        s1.y = fmaf(s1.y, alpha, pve * e1.y);
        s1.z = fmaf(s1.z, alpha, pve * e1.z);
        s1.w = fmaf(s1.w, alpha, pve * e1.w);
        m = mn;

        // e2n gating -> e_new: ai = sigmoid((dotd + dj - di)*em/8)
        float o0 = 0.f, o1 = 0.f;
        if (am) {
            float arg = (dotd + dj - di) * em * 0.125f;
            float ai = 1.f / (1.f + __expf(-arg));
            float aj = 1.f - ai;
            o0 = (ai * vnj.x + aj * vni.x) * em;
            o1 = (ai * vnj.y + aj * vni.y) * em;
        }
        __stcg(reinterpret_cast<float2*>(out_e + ((size_t)r * Nn + j) * DHh + 2 * lane),
               make_float2(o0, o1));

        j = jn;
        e0 = ne0; e1 = ne1; vj0 = nvj0; vj1 = nvj1; vnj = nvnj;
        xm_j = nxm_j; dj = ndj;
    }

    // merge the 8 warps' online-softmax partials
    __shared__ float s_sm[8][Dd];
    __shared__ float mw[8], lw[8], tw[8];
    s_sm[wid][d0 + 0] = s0.x; s_sm[wid][d0 + 1] = s0.y;
    s_sm[wid][d0 + 2] = s0.z; s_sm[wid][d0 + 3] = s0.w;
    s_sm[wid][d1 + 0] = s1.x; s_sm[wid][d1 + 1] = s1.y;
    s_sm[wid][d1 + 2] = s1.z; s_sm[wid][d1 + 3] = s1.w;
    if (lane == 0) { mw[wid] = m; lw[wid] = l; tw[wid] = tacc; }
    __syncthreads();

    float gm = mw[0];
    #pragma unroll
    for (int w = 1; w < 8; ++w) gm = fmaxf(gm, mw[w]);
    float gl = 0.f, gt = 0.f, gs = 0.f;
    #pragma unroll
    for (int w = 0; w < 8; ++w) {
        float sc2 = __expf(mw[w] - gm);
        gl = fmaf(lw[w], sc2, gl);
        gt = fmaf(tw[w], sc2, gt);
        gs = fmaf(s_sm[w][t], sc2, gs);
    }
    float invl = 1.f / gl;
    g_s[(size_t)r * Dd + t] = gs * invl;
    if (t == 0) g_t[r] = gt * invl;
}

// ------------------------------------------------------------------
// n2n self attention: one block per (b,i); PV split across 4 quarters
// ------------------------------------------------------------------
__global__ void self_attn_kernel(const float* __restrict__ mask)
{
    int r = blockIdx.x;
    int b = r >> 8;
    int t = threadIdx.x;

    __shared__ float Q_s[DHh];
    __shared__ float K_s[128][65];
    __shared__ float att[Nn];
    __shared__ float red[256];
    __shared__ float part[4][DHh];

    const float* Q = g_np + 3 * (size_t)BND;
    const float* K = g_np + 4 * (size_t)BND;
    const float* V = g_np + 5 * (size_t)BND;

    if (t < DHh) Q_s[t] = Q[(size_t)r * DHh + t];
    float xm_i = mask[r];
    float logit = 0.f;

    for (int tt = 0; tt < 2; ++tt) {
        __syncthreads();
        for (int idx = t; idx < 128 * 64; idx += 256) {
            int row = idx >> 6, col = idx & 63;
            K_s[row][col] = K[(size_t)(b * Nn + tt * 128 + row) * DHh + col];
        }
        __syncthreads();
        if ((t >> 7) == tt) {
            int row = t & 127;
            float a = 0.f;
            #pragma unroll 8
            for (int k = 0; k < DHh; ++k) a = fmaf(Q_s[k], K_s[row][k], a);
            logit = a;
        }
    }

    float xm_j = mask[b * Nn + t];
    bool am = (xm_i * xm_j) > 0.f;
    logit = am ? logit * 0.125f : -1e9f;

    red[t] = logit;
    __syncthreads();
    for (int o = 128; o; o >>= 1) {
        if (t < o) red[t] = fmaxf(red[t], red[t + o]);
        __syncthreads();
    }
    float mx = red[0];
    __syncthreads();
    float ex = __expf(logit - mx);
    red[t] = ex;
    __syncthreads();
    for (int o = 128; o; o >>= 1) {
        if (t < o) red[t] += red[t + o];
        __syncthreads();
    }
    float sm = red[0];
    att[t] = ex / sm;
    __syncthreads();

    // PV: quarter q handles j in [64q, 64q+64)
    int q = t >> 6, h = t & 63;
    float acc = 0.f;
    const float* Vb = V + (size_t)(b * Nn + q * 64) * DHh + h;
    #pragma unroll 8
    for (int jj = 0; jj < 64; ++jj)
        acc = fmaf(att[q * 64 + jj], Vb[(size_t)jj * DHh], acc);
    part[q][h] = acc;
    __syncthreads();
    if (t < DHh)
        g_xself[(size_t)r * DHh + t] =
            (part[0][t] + part[1][t] + part[2][t] + part[3][t]) * xm_i;
}

// ------------------------------------------------------------------
// x_cross = g_s @ Wv + g_t*bv ; x_out = [x_cross, x_self] @ Wmix + bmix
// grid = B*N, block = 256
// ------------------------------------------------------------------
__global__ void xcross_mix_kernel(const float* __restrict__ Wv,
                                  const float* __restrict__ bv,
                                  const float* __restrict__ Wmix,
                                  const float* __restrict__ bmix,
                                  float* __restrict__ out)
{
    int r = blockIdx.x, t = threadIdx.x;
    int q = t >> 6, h = t & 63;
    __shared__ float ssm[Dd];
    __shared__ float part[4][DHh];
    __shared__ float xc[DHh], xsf[DHh];

    ssm[t] = g_s[(size_t)r * Dd + t];
    if (t < DHh) xsf[t] = g_xself[(size_t)r * DHh + t];
    __syncthreads();

    float acc = (q == 0) ? g_t[r] * bv[h] : 0.f;
    #pragma unroll 8
    for (int d = 0; d < 64; ++d)
        acc = fmaf(ssm[q * 64 + d], Wv[(q * 64 + d) * DHh + h], acc);
    part[q][h] = acc;
    __syncthreads();
    if (t < DHh) xc[t] = part[0][t] + part[1][t] + part[2][t] + part[3][t];
    __syncthreads();

    // final mix: 64 outputs, split 128-dim dot across 2 halves
    if (t < 128) {
        int half = t >> 6, hh = t & 63;
        float o = (half == 0) ? bmix[hh] : 0.f;
        #pragma unroll 8
        for (int k = 0; k < 64; ++k) {
            float src = (half == 0) ? xc[k] : xsf[k];
            o = fmaf(src, Wmix[(half * 64 + k) * DHh + hh], o);
        }
        part[half][hh] = o;
    }
    __syncthreads();
    if (t < DHh) out[(size_t)r * DHh + t] = part[0][t] + part[1][t];
}

extern "C" void kernel_launch(void* const* d_in, const int* in_sizes, int n_in,
                              void* d_out, int out_size)
{
    const float* x       = (const float*)d_in[0];
    const float* e       = (const float*)d_in[1];
    const float* mask    = (const float*)d_in[2];
    const float* W_n2e_q = (const float*)d_in[3];  const float* b_n2e_q = (const float*)d_in[4];
    const float* W_n2e_k = (const float*)d_in[5];  const float* b_n2e_k = (const float*)d_in[6];
    const float* W_n2e_v = (const float*)d_in[7];  const float* b_n2e_v = (const float*)d_in[8];
    const float* W_e2n_q = (const float*)d_in[9];  const float* b_e2n_q = (const float*)d_in[10];
    const float* W_e2n_k = (const float*)d_in[11]; const float* b_e2n_k = (const float*)d_in[12];
    const float* W_e2n_v = (const float*)d_in[13]; const float* b_e2n_v = (const float*)d_in[14];
    const float* W_n2n_q = (const float*)d_in[15]; const float* b_n2n_q = (const float*)d_in[16];
    const float* W_n2n_k = (const float*)d_in[17]; const float* b_n2n_k = (const float*)d_in[18];
    const float* W_n2n_v = (const float*)d_in[19]; const float* b_n2n_v = (const float*)d_in[20];
    const float* W_mix   = (const float*)d_in[21]; const float* b_mix   = (const float*)d_in[22];

    float* out   = (float*)d_out;
    float* out_x = out;
    float* out_e = out + (size_t)Bn * Nn * DHh;

    proj_x_kernel<<<BNr, 384>>>(x, mask,
        W_n2e_q, b_n2e_q,
        W_e2n_k, b_e2n_k,
        W_e2n_v, b_e2n_v,
        W_n2n_q, b_n2n_q,
        W_n2n_k, b_n2n_k,
        W_n2n_v, b_n2n_v);

    transpose_w_kernel<<<DHh, Dd>>>(W_n2e_k, W_e2n_q);
    make_uv_kernel<<<BNr, Dd>>>(b_n2e_k, b_e2n_q);

    edge_kernel<<<BNr, 256>>>(e, mask, out_e);

    self_attn_kernel<<<BNr, 256>>>(mask);

    xcross_mix_kernel<<<BNr, 256>>>(W_n2e_v, b_n2e_v, W_mix, b_mix, out_x);
}

// round 5
// speedup vs baseline: 12.5373x; 1.1028x over previous
#include <cuda_runtime.h>
#include <math.h>

#define Bn 8
#define Nn 256
#define Dd 256
#define DHh 64
#define BND (Bn * Nn * DHh)      // 131072
#define BNr (Bn * Nn)            // 2048

// scratch: Qn,Kn,Vn,Q,K,V
__device__ float g_np[6 * BND];
// folded-weight per-row vectors
__device__ float g_u[BNr * Dd];    // Wk_n2e @ Qn_i
__device__ float g_v[BNr * Dd];    // Wq_e2n @ Kn_j
__device__ float g_c[BNr];         // bk_n2e . Qn_i
__device__ float g_d[BNr];         // bq_e2n . Kn_j
// transposed weights (h-major)
__device__ float g_Wkt[DHh * Dd];
__device__ float g_Wqt[DHh * Dd];

// Reduce two values across the warp in 6 shuffles:
// lanes<16 tree-reduce a-partials, lanes>=16 reduce b-partials, then swap.
__device__ __forceinline__ void dual_warp_sum(float& a, float& b_, int lane) {
    float send = (lane & 16) ? a : b_;
    float recv = __shfl_xor_sync(0xffffffffu, send, 16);
    float v = (lane & 16) ? (b_ + recv) : (a + recv);
    #pragma unroll
    for (int o = 8; o; o >>= 1) v += __shfl_xor_sync(0xffffffffu, v, o);
    float other = __shfl_xor_sync(0xffffffffu, v, 16);
    a  = (lane & 16) ? other : v;
    b_ = (lane & 16) ? v : other;
}

// ------------------------------------------------------------------
// 6 projections of x
// ------------------------------------------------------------------
__global__ void proj_x_kernel(
    const float* __restrict__ x, const float* __restrict__ mask,
    const float* __restrict__ W0, const float* __restrict__ b0,
    const float* __restrict__ W1, const float* __restrict__ b1,
    const float* __restrict__ W2, const float* __restrict__ b2,
    const float* __restrict__ W3, const float* __restrict__ b3,
    const float* __restrict__ W4, const float* __restrict__ b4,
    const float* __restrict__ W5, const float* __restrict__ b5)
{
    int r = blockIdx.x;
    int t = threadIdx.x;
    __shared__ float xs[Dd];
    if (t < Dd) xs[t] = x[(size_t)r * Dd + t];
    __syncthreads();

    int p = t >> 6, h = t & 63;
    const float* W;
    const float* bb;
    switch (p) {
        case 0: W = W0; bb = b0; break;
        case 1: W = W1; bb = b1; break;
        case 2: W = W2; bb = b2; break;
        case 3: W = W3; bb = b3; break;
        case 4: W = W4; bb = b4; break;
        default: W = W5; bb = b5; break;
    }
    float acc = bb[h];
    #pragma unroll 8
    for (int k = 0; k < Dd; ++k) acc = fmaf(xs[k], W[k * DHh + h], acc);
    g_np[(size_t)p * BND + (size_t)r * DHh + h] = acc * mask[r];
}

__global__ void transpose_w_kernel(const float* __restrict__ Wk,
                                   const float* __restrict__ Wq)
{
    int h = blockIdx.x;
    int d = threadIdx.x;
    g_Wkt[h * Dd + d] = Wk[d * DHh + h];
    g_Wqt[h * Dd + d] = Wq[d * DHh + h];
}

__global__ void make_uv_kernel(const float* __restrict__ bk,
                               const float* __restrict__ bq)
{
    int r = blockIdx.x;
    int t = threadIdx.x;    // 256
    __shared__ float qn[DHh], kn[DHh], pc[DHh], pd[DHh];
    if (t < DHh) {
        float q = g_np[(size_t)r * DHh + t];
        float k = g_np[(size_t)BND + (size_t)r * DHh + t];
        qn[t] = q; kn[t] = k;
        pc[t] = bk[t] * q;
        pd[t] = bq[t] * k;
    }
    __syncthreads();
    float au = 0.f, av = 0.f;
    #pragma unroll 8
    for (int h = 0; h < DHh; ++h) {
        au = fmaf(g_Wkt[h * Dd + t], qn[h], au);
        av = fmaf(g_Wqt[h * Dd + t], kn[h], av);
    }
    g_u[(size_t)r * Dd + t] = au;
    g_v[(size_t)r * Dd + t] = av;
    if (t == 0) {
        float sc = 0.f, sd2 = 0.f;
        #pragma unroll
        for (int h = 0; h < DHh; ++h) { sc += pc[h]; sd2 += pd[h]; }
        g_c[r] = sc;
        g_d[r] = sd2;
    }
}

// ------------------------------------------------------------------
// Fused mega-kernel: per (b,i) block does
//   phase 1: stream e row-slab -> e_new, online-softmax weighted e-sum
//   phase 2: n2n self attention row
//   phase 3: x_cross = s@Wv + t*bv ; out_x = [xc,xs]@Wmix + bmix
// ------------------------------------------------------------------
__global__ void __launch_bounds__(256, 4) fused_kernel(
    const float* __restrict__ e, const float* __restrict__ mask,
    const float* __restrict__ Wv, const float* __restrict__ bv,
    const float* __restrict__ Wmix, const float* __restrict__ bmix,
    float* __restrict__ out_e, float* __restrict__ out_x)
{
    int r = blockIdx.x;
    int b = r >> 8;
    int t = threadIdx.x;
    int wid = t >> 5, lane = t & 31;

    // big buffer: phase1 = s_sm[8][256] (2048 floats), phase2 = K_s[128][65]
    __shared__ float big[128 * 65];
    __shared__ float maskb_s[Nn];
    __shared__ float djs_s[Nn];
    __shared__ float mw[8], lw[8], tw[8];
    __shared__ float gsrow[Dd];
    __shared__ float gt_s;
    __shared__ float Q_s[DHh];
    __shared__ float att[Nn];
    __shared__ float red[256];
    __shared__ float part[4][DHh];
    __shared__ float xsf_s[DHh], xc_s[DHh];

    const float* Vn = g_np + 2 * (size_t)BND;

    maskb_s[t] = mask[b * Nn + t];
    djs_s[t]   = g_d[b * Nn + t];
    __syncthreads();

    int d0 = 4 * lane;
    int d1 = 128 + 4 * lane;

    const float4 u0  = *reinterpret_cast<const float4*>(g_u + (size_t)r * Dd + d0);
    const float4 u1  = *reinterpret_cast<const float4*>(g_u + (size_t)r * Dd + d1);
    const float4 vi0 = *reinterpret_cast<const float4*>(g_v + (size_t)r * Dd + d0);
    const float4 vi1 = *reinterpret_cast<const float4*>(g_v + (size_t)r * Dd + d1);
    const float c_i  = g_c[r];
    const float di   = g_d[r];
    const float xm_i = mask[r];
    const float2 vni = *reinterpret_cast<const float2*>(Vn + (size_t)r * DHh + 2 * lane);

    float m = -INFINITY, l = 0.f, tacc = 0.f;
    float4 s0 = make_float4(0.f, 0.f, 0.f, 0.f);
    float4 s1 = make_float4(0.f, 0.f, 0.f, 0.f);

    const float* erow = e + (size_t)r * Nn * Dd;

    // ---- phase 1: edge streaming loop ----
    int j = wid;
    float4 e0 = __ldcs(reinterpret_cast<const float4*>(erow + (size_t)j * Dd + d0));
    float4 e1 = __ldcs(reinterpret_cast<const float4*>(erow + (size_t)j * Dd + d1));

    for (; j < Nn; ) {
        int jn = j + 8;
        float4 ne0, ne1;
        if (jn < Nn) {
            ne0 = __ldcs(reinterpret_cast<const float4*>(erow + (size_t)jn * Dd + d0));
            ne1 = __ldcs(reinterpret_cast<const float4*>(erow + (size_t)jn * Dd + d1));
        }
        float4 vj0 = *reinterpret_cast<const float4*>(g_v + (size_t)(b * Nn + j) * Dd + d0);
        float4 vj1 = *reinterpret_cast<const float4*>(g_v + (size_t)(b * Nn + j) * Dd + d1);
        float2 vnj = *reinterpret_cast<const float2*>(Vn + (size_t)(b * Nn + j) * DHh + 2 * lane);
        float xm_j = maskb_s[j];
        float dj   = djs_s[j];

        // vdiff = v_j - v_i
        float4 w0, w1;
        w0.x = vj0.x - vi0.x; w0.y = vj0.y - vi0.y;
        w0.z = vj0.z - vi0.z; w0.w = vj0.w - vi0.w;
        w1.x = vj1.x - vi1.x; w1.y = vj1.y - vi1.y;
        w1.z = vj1.z - vi1.z; w1.w = vj1.w - vi1.w;

        float dot0, dotd;
        dot0 = e0.x * u0.x;              dot0 = fmaf(e0.y, u0.y, dot0);
        dot0 = fmaf(e0.z, u0.z, dot0);   dot0 = fmaf(e0.w, u0.w, dot0);
        dot0 = fmaf(e1.x, u1.x, dot0);   dot0 = fmaf(e1.y, u1.y, dot0);
        dot0 = fmaf(e1.z, u1.z, dot0);   dot0 = fmaf(e1.w, u1.w, dot0);
        dotd = e0.x * w0.x;              dotd = fmaf(e0.y, w0.y, dotd);
        dotd = fmaf(e0.z, w0.z, dotd);   dotd = fmaf(e0.w, w0.w, dotd);
        dotd = fmaf(e1.x, w1.x, dotd);   dotd = fmaf(e1.y, w1.y, dotd);
        dotd = fmaf(e1.z, w1.z, dotd);   dotd = fmaf(e1.w, w1.w, dotd);

        dual_warp_sum(dot0, dotd, lane);

        float em = xm_i * xm_j;
        bool am = em > 0.f;

        // n2e online softmax + weighted-e accumulation
        float sc = am ? (dot0 + c_i) * em * 0.125f : -1e9f;
        float mn = fmaxf(m, sc);
        float alpha = __expf(m - mn);
        float pv = __expf(sc - mn);
        l = l * alpha + pv;
        float pve = pv * em;
        tacc = tacc * alpha + pve;
        s0.x = fmaf(s0.x, alpha, pve * e0.x);
        s0.y = fmaf(s0.y, alpha, pve * e0.y);
        s0.z = fmaf(s0.z, alpha, pve * e0.z);
        s0.w = fmaf(s0.w, alpha, pve * e0.w);
        s1.x = fmaf(s1.x, alpha, pve * e1.x);
        s1.y = fmaf(s1.y, alpha, pve * e1.y);
        s1.z = fmaf(s1.z, alpha, pve * e1.z);
        s1.w = fmaf(s1.w, alpha, pve * e1.w);
        m = mn;

        // e2n gating -> e_new: ai = sigmoid((dotd + dj - di)*em/8)
        float o0 = 0.f, o1 = 0.f;
        if (am) {
            float arg = (dotd + dj - di) * em * 0.125f;
            float ai = 1.f / (1.f + __expf(-arg));
            float aj = 1.f - ai;
            o0 = (ai * vnj.x + aj * vni.x) * em;
            o1 = (ai * vnj.y + aj * vni.y) * em;
        }
        __stcg(reinterpret_cast<float2*>(out_e + ((size_t)r * Nn + j) * DHh + 2 * lane),
               make_float2(o0, o1));

        j = jn;
        e0 = ne0; e1 = ne1;
    }

    // merge the 8 warps' online-softmax partials (s_sm = big[w*Dd + d])
    big[wid * Dd + d0 + 0] = s0.x; big[wid * Dd + d0 + 1] = s0.y;
    big[wid * Dd + d0 + 2] = s0.z; big[wid * Dd + d0 + 3] = s0.w;
    big[wid * Dd + d1 + 0] = s1.x; big[wid * Dd + d1 + 1] = s1.y;
    big[wid * Dd + d1 + 2] = s1.z; big[wid * Dd + d1 + 3] = s1.w;
    if (lane == 0) { mw[wid] = m; lw[wid] = l; tw[wid] = tacc; }
    __syncthreads();

    {
        float gm = mw[0];
        #pragma unroll
        for (int w = 1; w < 8; ++w) gm = fmaxf(gm, mw[w]);
        float gl = 0.f, gt = 0.f, gs = 0.f;
        #pragma unroll
        for (int w = 0; w < 8; ++w) {
            float sc2 = __expf(mw[w] - gm);
            gl = fmaf(lw[w], sc2, gl);
            gt = fmaf(tw[w], sc2, gt);
            gs = fmaf(big[w * Dd + t], sc2, gs);
        }
        float invl = 1.f / gl;
        gsrow[t] = gs * invl;
        if (t == 0) gt_s = gt * invl;
    }

    // ---- phase 2: n2n self attention for row r ----
    const float* Q = g_np + 3 * (size_t)BND;
    const float* K = g_np + 4 * (size_t)BND;
    const float* V = g_np + 5 * (size_t)BND;

    if (t < DHh) Q_s[t] = Q[(size_t)r * DHh + t];

    // QK^T row: 2 tiles of 128 K-rows; all 256 threads active (half-dim split)
    for (int tt = 0; tt < 2; ++tt) {
        __syncthreads();  // big free / red free
        for (int idx = t; idx < 128 * 64; idx += 256) {
            int row = idx >> 6, col = idx & 63;
            big[row * 65 + col] = K[(size_t)(b * Nn + tt * 128 + row) * DHh + col];
        }
        __syncthreads();
        int row = t & 127, half = t >> 7;
        float p = 0.f;
        #pragma unroll 8
        for (int d = 0; d < 32; ++d)
            p = fmaf(Q_s[half * 32 + d], big[row * 65 + half * 32 + d], p);
        red[t] = p;
        __syncthreads();
        if (t < 128) att[tt * 128 + t] = red[t] + red[t + 128];
    }
    __syncthreads();

    // masked softmax over the 256 logits (thread t owns j=t)
    {
        float xm_j = maskb_s[t];
        bool am = (xm_i * xm_j) > 0.f;
        float lg = am ? att[t] * 0.125f : -1e9f;
        float wmax = lg;
        #pragma unroll
        for (int o = 16; o; o >>= 1)
            wmax = fmaxf(wmax, __shfl_xor_sync(0xffffffffu, wmax, o));
        if (lane == 0) red[wid] = wmax;
        __syncthreads();
        float gmax = red[0];
        #pragma unroll
        for (int w = 1; w < 8; ++w) gmax = fmaxf(gmax, red[w]);
        float ex = __expf(lg - gmax);
        float wsum = ex;
        #pragma unroll
        for (int o = 16; o; o >>= 1)
            wsum += __shfl_xor_sync(0xffffffffu, wsum, o);
        if (lane == 0) red[8 + wid] = wsum;
        __syncthreads();
        float gsum = 0.f;
        #pragma unroll
        for (int w = 0; w < 8; ++w) gsum += red[8 + w];
        att[t] = ex / gsum;
    }
    __syncthreads();

    // PV: quarter q handles j in [64q, 64q+64)
    {
        int q = t >> 6, h = t & 63;
        float acc = 0.f;
        const float* Vb = V + (size_t)(b * Nn + q * 64) * DHh + h;
        #pragma unroll 8
        for (int jj = 0; jj < 64; ++jj)
            acc = fmaf(att[q * 64 + jj], Vb[(size_t)jj * DHh], acc);
        part[q][h] = acc;
    }
    __syncthreads();
    if (t < DHh)
        xsf_s[t] = (part[0][t] + part[1][t] + part[2][t] + part[3][t]) * xm_i;
    __syncthreads();

    // ---- phase 3: x_cross = gsrow@Wv + gt*bv ; out = [xc,xs]@Wmix + bmix ----
    {
        int q = t >> 6, h = t & 63;
        float acc = (q == 0) ? gt_s * bv[h] : 0.f;
        #pragma unroll 8
        for (int d = 0; d < 64; ++d)
            acc = fmaf(gsrow[q * 64 + d], Wv[(q * 64 + d) * DHh + h], acc);
        part[q][h] = acc;
    }
    __syncthreads();
    if (t < DHh) xc_s[t] = part[0][t] + part[1][t] + part[2][t] + part[3][t];
    __syncthreads();

    if (t < 128) {
        int half = t >> 6, hh = t & 63;
        float o = (half == 0) ? bmix[hh] : 0.f;
        #pragma unroll 8
        for (int k = 0; k < 64; ++k) {
            float src = (half == 0) ? xc_s[k] : xsf_s[k];
            o = fmaf(src, Wmix[(half * 64 + k) * DHh + hh], o);
        }
        part[half][hh] = o;
    }
    __syncthreads();
    if (t < DHh) out_x[(size_t)r * DHh + t] = part[0][t] + part[1][t];
}

extern "C" void kernel_launch(void* const* d_in, const int* in_sizes, int n_in,
                              void* d_out, int out_size)
{
    const float* x       = (const float*)d_in[0];
    const float* e       = (const float*)d_in[1];
    const float* mask    = (const float*)d_in[2];
    const float* W_n2e_q = (const float*)d_in[3];  const float* b_n2e_q = (const float*)d_in[4];
    const float* W_n2e_k = (const float*)d_in[5];  const float* b_n2e_k = (const float*)d_in[6];
    const float* W_n2e_v = (const float*)d_in[7];  const float* b_n2e_v = (const float*)d_in[8];
    const float* W_e2n_q = (const float*)d_in[9];  const float* b_e2n_q = (const float*)d_in[10];
    const float* W_e2n_k = (const float*)d_in[11]; const float* b_e2n_k = (const float*)d_in[12];
    const float* W_e2n_v = (const float*)d_in[13]; const float* b_e2n_v = (const float*)d_in[14];
    const float* W_n2n_q = (const float*)d_in[15]; const float* b_n2n_q = (const float*)d_in[16];
    const float* W_n2n_k = (const float*)d_in[17]; const float* b_n2n_k = (const float*)d_in[18];
    const float* W_n2n_v = (const float*)d_in[19]; const float* b_n2n_v = (const float*)d_in[20];
    const float* W_mix   = (const float*)d_in[21]; const float* b_mix   = (const float*)d_in[22];

    float* out   = (float*)d_out;
    float* out_x = out;
    float* out_e = out + (size_t)Bn * Nn * DHh;

    proj_x_kernel<<<BNr, 384>>>(x, mask,
        W_n2e_q, b_n2e_q,
        W_e2n_k, b_e2n_k,
        W_e2n_v, b_e2n_v,
        W_n2n_q, b_n2n_q,
        W_n2n_k, b_n2n_k,
        W_n2n_v, b_n2n_v);

    transpose_w_kernel<<<DHh, Dd>>>(W_n2e_k, W_e2n_q);
    make_uv_kernel<<<BNr, Dd>>>(b_n2e_k, b_e2n_q);

    fused_kernel<<<BNr, 256>>>(e, mask,
        W_n2e_v, b_n2e_v, W_mix, b_mix, out_e, out_x);
}